// round 6
// baseline (speedup 1.0000x reference)
#include <cuda_runtime.h>
#include <math.h>

#define MAXN     1024
#define NSHIFT   27
#define NKDIM    17
#define NLINES   145          // half-space (fx,fy) lines: (0,0) + (0,1..8) + (1..8, -8..8)
#define NB_RECIP 73           // ceil(145 / 2) ; 2 lines per 512-thread block
#define SELF_BID NB_RECIP
#define REAL_BID0 (NB_RECIP + 1)

// -------- device accumulators (zero at load; finalizer re-zeros each run) ----
__device__ double   g_acc_real, g_acc_recip, g_acc_self;
__device__ unsigned g_ticket;

// fast erfc: Abramowitz & Stegun 7.1.26, |abs err| <= 1.5e-7
__device__ __forceinline__ float erfc_fast(float x)
{
    float t = __fdividef(1.0f, fmaf(0.3275911f, x, 1.0f));
    float p = t * fmaf(t, fmaf(t, fmaf(t, fmaf(t, 1.061405429f, -1.453152027f),
                        1.421413741f), -0.284496736f), 0.254829592f);
    return p * __expf(-x * x);
}

// line index -> (fx, fy)
__device__ __forceinline__ void line_to_fxy(int line, int& fx, int& fy)
{
    if (line == 0)      { fx = 0; fy = 0; }
    else if (line <= 8) { fx = 0; fy = line; }
    else { int u = line - 9; fx = u / 17 + 1; fy = u % 17 - 8; }
}

__global__ void __launch_bounds__(512, 2) k_main(
    const float* __restrict__ pos,     const float* __restrict__ cell,
    const float* __restrict__ charges, const float* __restrict__ sigtab,
    const int*   __restrict__ species, int n, int npairs,
    float* __restrict__ out, int grid)
{
    __shared__ float4 sbuf[MAXN];          // real: posq ; recip: (t0,t1,t2,q)
    __shared__ float  ssig[MAXN];
    __shared__ float4 sshift[NSHIFT];      // xyz shift, w = |s|^2
    __shared__ float  spc[2][4][17], sps[2][4][17];
    __shared__ float  searr[40];
    __shared__ double sred[16];

    const int tid = threadIdx.x;
    const int bid = blockIdx.x;

    // ---- uniform fp32 scalar setup (every thread, every block) ----
    float c00 = cell[0], c01 = cell[1], c02 = cell[2];
    float c10 = cell[3], c11 = cell[4], c12 = cell[5];
    float c20 = cell[6], c21 = cell[7], c22 = cell[8];

    float cof00 =  (c11*c22 - c12*c21);
    float cof01 = -(c10*c22 - c12*c20);
    float cof02 =  (c10*c21 - c11*c20);
    float cof10 = -(c01*c22 - c02*c21);
    float cof11 =  (c00*c22 - c02*c20);
    float cof12 = -(c00*c21 - c01*c20);
    float cof20 =  (c01*c12 - c02*c11);
    float cof21 = -(c00*c12 - c02*c10);
    float cof22 =  (c00*c11 - c01*c10);

    float det = c00*cof00 + c01*cof01 + c02*cof02;
    float vol = fabsf(det);

    const float TWO_PI = 6.2831853071795864769f;
    float eta = powf(vol * vol / (float)n, 1.0f / 6.0f) * rsqrtf(TWO_PI);
    float inv_s2eta  = 1.0f / (1.4142135623730951f * eta);
    // tightened real cutoff: arg_eta < 4  ->  r^2 < 32 eta^2  (erfc(4)=1.5e-8,
    // below the A&S approximation error; reference cutoff is 36.84 eta^2)
    float cut2_eff   = 32.0f * eta * eta;
    const float SQRT_2LOG = 6.0697086f;   // sqrt(-2 ln 1e-8)
    float cutk = SQRT_2LOG / eta;
    float cut2_recip = cutk * cutk;

    if (bid < NB_RECIP) {
        // ======================= reciprocal =======================
        float idet = 1.0f / det;
        float r00 = TWO_PI*cof00*idet, r01 = TWO_PI*cof01*idet, r02 = TWO_PI*cof02*idet;
        float r10 = TWO_PI*cof10*idet, r11 = TWO_PI*cof11*idet, r12 = TWO_PI*cof12*idet;
        float r20 = TWO_PI*cof20*idet, r21 = TWO_PI*cof21*idet, r22 = TWO_PI*cof22*idet;

        // stage (t0,t1,t2,q) per atom: t_a = row_a . p
        for (int i = tid; i < n; i += 512) {
            float px = pos[3*i], py = pos[3*i+1], pz = pos[3*i+2];
            float q  = charges[i];
            sbuf[i] = make_float4(fmaf(px,r00,fmaf(py,r01,pz*r02)),
                                  fmaf(px,r10,fmaf(py,r11,pz*r12)),
                                  fmaf(px,r20,fmaf(py,r21,pz*r22)), q);
        }
        __syncthreads();

        int wid  = tid >> 5, lane = tid & 31;
        int l    = wid >> 3;          // line-in-block 0..1
        int sub  = wid & 7;
        int h    = sub >> 2;          // m-half: 0 -> fz -8..0, 1 -> fz 1..8
        int s4   = sub & 3;           // atom slice
        int line = bid * 2 + l;

        float qc[9], qs[9];
        #pragma unroll
        for (int e = 0; e < 9; e++) { qc[e] = 0.f; qs[e] = 0.f; }

        if (line < NLINES) {
            int fx, fy; line_to_fxy(line, fx, fy);
            float ffx = (float)fx, ffy = (float)fy;
            float moff = (float)(h * 9 - 8);

            for (int a = lane + s4*32; a < n; a += 128) {
                float4 tq = sbuf[a];
                float base = fmaf(ffx, tq.x, fmaf(ffy, tq.y, moff * tq.z));
                float c, s, ct, st;
                __sincosf(base, &s, &c);
                __sincosf(tq.z, &st, &ct);
                #pragma unroll
                for (int e = 0; e < 9; e++) {
                    qc[e] = fmaf(tq.w, c, qc[e]);
                    qs[e] = fmaf(tq.w, s, qs[e]);
                    float cn = fmaf(c, ct, -s*st);
                    s        = fmaf(s, ct,  c*st);
                    c = cn;
                }
            }
            #pragma unroll
            for (int e = 0; e < 9; e++) {
                #pragma unroll
                for (int off = 16; off; off >>= 1) {
                    qc[e] += __shfl_down_sync(0xFFFFFFFFu, qc[e], off);
                    qs[e] += __shfl_down_sync(0xFFFFFFFFu, qs[e], off);
                }
            }
            if (lane == 0) {
                int mb  = h * 9;
                int cnt = h ? 8 : 9;     // h=1, e=8 would be fz=9: discard
                for (int e = 0; e < cnt; e++) {
                    spc[l][s4][mb + e] = qc[e];
                    sps[l][s4][mb + e] = qs[e];
                }
            }
        }
        __syncthreads();

        if (tid < 34) {
            int l2 = tid / 17, m = tid % 17;
            int line2 = bid * 2 + l2;
            float e = 0.f;
            if (line2 < NLINES) {
                int fx2, fy2; line_to_fxy(line2, fx2, fy2);
                float w2 = (line2 == 0) ? 1.f : 2.f;   // line + its negation
                float ffx = (float)fx2, ffy = (float)fy2, ffz = (float)(m - 8);
                float kx = ffx*r00 + ffy*r10 + ffz*r20;
                float ky = ffx*r01 + ffy*r11 + ffz*r21;
                float kz = ffx*r02 + ffy*r12 + ffz*r22;
                float k2 = fmaf(kx, kx, fmaf(ky, ky, kz*kz));
                if (k2 > 1e-16f && k2 < cut2_recip) {
                    float wk = __fdividef(__expf(-0.5f * eta * eta * k2), k2);
                    float C = spc[l2][0][m] + spc[l2][1][m] + spc[l2][2][m] + spc[l2][3][m];
                    float S = sps[l2][0][m] + sps[l2][1][m] + sps[l2][2][m] + sps[l2][3][m];
                    e = w2 * wk * fmaf(C, C, S*S);
                }
            }
            searr[tid] = e;
        }
        __syncthreads();
        if (tid == 0) {
            double v = 0.0;
            for (int q2 = 0; q2 < 34; q2++) v += (double)searr[q2];
            if (v != 0.0) atomicAdd(&g_acc_recip, v);
        }
    }
    else if (bid == SELF_BID) {
        // ================= self + diagonal real-space =================
        if (tid < NSHIFT) {
            float sx = (float)(tid/9 - 1), sy = (float)((tid/3)%3 - 1), sz = (float)(tid%3 - 1);
            float x = sx*c00 + sy*c10 + sz*c20;
            float y = sx*c01 + sy*c11 + sz*c21;
            float z = sx*c02 + sy*c12 + sz*c22;
            sshift[tid] = make_float4(x, y, z, fmaf(x,x,fmaf(y,y,z*z)));
        }
        __syncthreads();

        float t0s = __fdividef(-0.7978845608f, eta);   // -sqrt(2/pi)/eta
        const float c0 = 0.5641895835f;                // 1/sqrt(pi)

        float acc = 0.f;
        for (int i = tid; i < n; i += 512) {
            float q   = charges[i];
            float sig = sigtab[species[i]];
            float v   = t0s + __fdividef(c0, sig);
            float invgam = rsqrtf(4.0f * sig * sig);   // 1/(sqrt2 * sqrt(2 sig^2))
            #pragma unroll
            for (int m = 0; m < NSHIFT; m++) {
                float r2 = sshift[m].w;
                if (r2 > 1e-16f && r2 < cut2_eff) {
                    float rinv = rsqrtf(r2);
                    float r    = r2 * rinv;
                    float eg   = (r * invgam < 4.0f) ? erfc_fast(r * invgam) : 0.f;
                    v = fmaf(erfc_fast(r * inv_s2eta) - eg, rinv, v);
                }
            }
            acc = fmaf(q*q, v, acc);
        }
        #pragma unroll
        for (int off = 16; off; off >>= 1)
            acc += __shfl_down_sync(0xFFFFFFFFu, acc, off);
        int warp = tid >> 5;
        if ((tid & 31) == 0) sred[warp] = (double)acc;
        __syncthreads();
        if (tid == 0) {
            double v = 0.0;
            for (int w = 0; w < 16; w++) v += sred[w];
            atomicAdd(&g_acc_self, v);
        }
    }
    else {
        // ======================= real-space pairs =======================
        for (int i = tid; i < n; i += 512) {
            sbuf[i] = make_float4(pos[3*i], pos[3*i+1], pos[3*i+2], charges[i]);
            ssig[i] = sigtab[species[i]];
        }
        if (tid < NSHIFT) {
            float sx = (float)(tid/9 - 1), sy = (float)((tid/3)%3 - 1), sz = (float)(tid%3 - 1);
            float x = sx*c00 + sy*c10 + sz*c20;
            float y = sx*c01 + sy*c11 + sz*c21;
            float z = sx*c02 + sy*c12 + sz*c22;
            sshift[tid] = make_float4(x, y, z, fmaf(x,x,fmaf(y,y,z*z)));
        }
        __syncthreads();

        int t = (bid - REAL_BID0) * 512 + tid;
        float contrib = 0.f;
        if (t < npairs) {
            // decode t -> (i, j), j < i ; 8t+1 < 2^24 exact in fp32
            int i = (int)((1.0f + sqrtf(1.0f + 8.0f * (float)t)) * 0.5f);
            while (i * (i - 1) / 2 > t) i--;
            while ((i + 1) * i / 2 <= t) i++;
            int j = t - i * (i - 1) / 2;

            float4 a = sbuf[i];
            float4 b = sbuf[j];
            float dx = b.x - a.x, dy = b.y - a.y, dz = b.z - a.z;
            float si = ssig[i], sj = ssig[j];
            float inv_s2gam = rsqrtf(2.0f * fmaf(si, si, sj * sj));

            bool diagcell = (c01 == 0.f && c02 == 0.f && c10 == 0.f &&
                             c12 == 0.f && c20 == 0.f && c21 == 0.f);
            unsigned mask = 0u;
            if (diagcell) {
                // separable per-axis candidate filter (bit b <-> s = b-1)
                unsigned mx = 0u, my = 0u, mz = 0u;
                float v0;
                v0 = dx - c00; if (v0*v0 < cut2_eff) mx |= 1u;
                v0 = dx;       if (v0*v0 < cut2_eff) mx |= 2u;
                v0 = dx + c00; if (v0*v0 < cut2_eff) mx |= 4u;
                v0 = dy - c11; if (v0*v0 < cut2_eff) my |= 1u;
                v0 = dy;       if (v0*v0 < cut2_eff) my |= 2u;
                v0 = dy + c11; if (v0*v0 < cut2_eff) my |= 4u;
                v0 = dz - c22; if (v0*v0 < cut2_eff) mz |= 1u;
                v0 = dz;       if (v0*v0 < cut2_eff) mz |= 2u;
                v0 = dz + c22; if (v0*v0 < cut2_eff) mz |= 4u;
                unsigned myz = ((my & 1u) ? mz : 0u)
                             | ((my & 2u) ? (mz << 3) : 0u)
                             | ((my & 4u) ? (mz << 6) : 0u);
                mask = ((mx & 1u) ? myz : 0u)
                     | ((mx & 2u) ? (myz << 9)  : 0u)
                     | ((mx & 4u) ? (myz << 18) : 0u);
            } else {
                #pragma unroll
                for (int m = 0; m < NSHIFT; m++) {
                    float ddx = dx + sshift[m].x;
                    float ddy = dy + sshift[m].y;
                    float ddz = dz + sshift[m].z;
                    float r2  = fmaf(ddx, ddx, fmaf(ddy, ddy, ddz*ddz));
                    if (r2 > 1e-16f && r2 < cut2_eff) mask |= (1u << m);
                }
            }

            float s = 0.f;
            while (mask) {
                int m = __ffs(mask) - 1;
                mask &= mask - 1;
                float4 sm = sshift[m];
                float ddx = dx + sm.x;
                float ddy = dy + sm.y;
                float ddz = dz + sm.z;
                float r2  = fmaf(ddx, ddx, fmaf(ddy, ddy, ddz*ddz));
                if (r2 > 1e-16f && r2 < cut2_eff) {
                    float rinv = rsqrtf(r2);
                    float r    = r2 * rinv;
                    float ag   = r * inv_s2gam;
                    float eg   = (ag < 4.0f) ? erfc_fast(ag) : 0.f;
                    s = fmaf(erfc_fast(r * inv_s2eta) - eg, rinv, s);
                }
            }
            contrib = 2.f * s * a.w * b.w;
        }

        #pragma unroll
        for (int off = 16; off; off >>= 1)
            contrib += __shfl_down_sync(0xFFFFFFFFu, contrib, off);
        int warp = tid >> 5;
        if ((tid & 31) == 0) sred[warp] = (double)contrib;
        __syncthreads();
        if (tid < 32) {
            double v = (tid < 16) ? sred[tid] : 0.0;
            #pragma unroll
            for (int off = 8; off; off >>= 1)
                v += __shfl_down_sync(0xFFFFFFFFu, v, off);
            if (tid == 0 && v != 0.0) atomicAdd(&g_acc_real, v);
        }
    }

    // ---- last block to finish: finalize + reset for next graph replay ----
    __syncthreads();
    if (tid == 0) {
        __threadfence();
        unsigned ticket = atomicAdd(&g_ticket, 1u);
        if (ticket == (unsigned)grid - 1u) {
            const double COEF    = 14.399645478425668;
            const double FOUR_PI = 12.566370614359172953850573533118;
            double ar = *(volatile double*)&g_acc_real;
            double ak = *(volatile double*)&g_acc_recip;
            double as = *(volatile double*)&g_acc_self;
            double e  = 0.5 * COEF * (ar + as + (FOUR_PI / (double)vol) * ak);
            out[0] = (float)e;
            g_acc_real = 0.0; g_acc_recip = 0.0; g_acc_self = 0.0;
            g_ticket = 0u;
        }
    }
}

extern "C" void kernel_launch(void* const* d_in, const int* in_sizes, int n_in,
                              void* d_out, int out_size)
{
    const float* pos     = (const float*)d_in[0];
    const float* cell    = (const float*)d_in[1];
    const float* charges = (const float*)d_in[2];
    const float* sigtab  = (const float*)d_in[3];
    const int*   species = (const int*)  d_in[4];

    int n = in_sizes[0] / 3;
    int npairs  = n * (n - 1) / 2;
    int nb_real = (npairs + 511) / 512;
    int grid    = REAL_BID0 + nb_real;

    k_main<<<grid, 512>>>(pos, cell, charges, sigtab, species,
                          n, npairs, (float*)d_out, grid);
}

// round 8
// speedup vs baseline: 1.1511x; 1.1511x over previous
#include <cuda_runtime.h>
#include <math.h>

#define MAXN     1024
#define NSHIFT   27
#define NKDIM    17
#define NLINES   145          // half-space (fx,fy) lines: (0,0) + (0,1..8) + (1..8, -8..8)
#define NB_RECIP 73           // 2 lines per 512-thread block
#define SELF_BID NB_RECIP
#define REAL_BID0 (NB_RECIP + 1)

// -------- device globals --------
__device__ float4 g_posq[MAXN];        // x,y,z,q
__device__ float4 g_tq[MAXN];          // recip theta factors (t0,t1,t2,q)
__device__ float  g_sig[MAXN];
__device__ float4 g_shift[NSHIFT];     // xyz shift, w=|s|^2
__device__ float  g_recipm[9];
__device__ float  g_eta, g_inv_s2eta, g_cut2_eff, g_cut2_recip, g_vol;
__device__ float  g_cdiag[3];
__device__ int    g_isdiag;
__device__ double g_acc_real, g_acc_recip, g_acc_self;
__device__ unsigned g_ticket;

// fast erfc: Abramowitz & Stegun 7.1.26, |abs err| <= 1.5e-7
__device__ __forceinline__ float erfc_fast(float x)
{
    float t = __fdividef(1.0f, fmaf(0.3275911f, x, 1.0f));
    float p = t * fmaf(t, fmaf(t, fmaf(t, fmaf(t, 1.061405429f, -1.453152027f),
                        1.421413741f), -0.284496736f), 0.254829592f);
    return p * __expf(-x * x);
}

__device__ __forceinline__ void line_to_fxy(int line, int& fx, int& fy)
{
    if (line == 0)      { fx = 0; fy = 0; }
    else if (line <= 8) { fx = 0; fy = line; }
    else { int u = line - 9; fx = u / 17 + 1; fy = u % 17 - 8; }
}

// -------- setup: one block, 768 threads, all fp32 --------
__global__ void __launch_bounds__(768) k_setup(
    const float* __restrict__ cell,  const float* __restrict__ sigtab,
    const float* __restrict__ pos,   const float* __restrict__ charges,
    const int*   __restrict__ species, int n)
{
    __shared__ float s_r[9];
    int tid = threadIdx.x;

    if (tid == 0) {
        float c00 = cell[0], c01 = cell[1], c02 = cell[2];
        float c10 = cell[3], c11 = cell[4], c12 = cell[5];
        float c20 = cell[6], c21 = cell[7], c22 = cell[8];

        float cof00 =  (c11*c22 - c12*c21);
        float cof01 = -(c10*c22 - c12*c20);
        float cof02 =  (c10*c21 - c11*c20);
        float cof10 = -(c01*c22 - c02*c21);
        float cof11 =  (c00*c22 - c02*c20);
        float cof12 = -(c00*c21 - c01*c20);
        float cof20 =  (c01*c12 - c02*c11);
        float cof21 = -(c00*c12 - c02*c10);
        float cof22 =  (c00*c11 - c01*c10);

        float det = c00*cof00 + c01*cof01 + c02*cof02;
        float vol = fabsf(det);
        g_vol = vol;

        const float TWO_PI = 6.2831853071795864769f;
        float eta = powf(vol * vol / (float)n, 1.0f / 6.0f) * rsqrtf(TWO_PI);
        g_eta       = eta;
        g_inv_s2eta = 1.0f / (1.4142135623730951f * eta);
        // tightened: arg_eta < 4 -> erfc < 1.5e-8 (below approx error); ref cut is 36.84 eta^2
        g_cut2_eff  = 32.0f * eta * eta;
        const float SQRT_2LOG = 6.0697086f;
        float cutk = SQRT_2LOG / eta;
        g_cut2_recip = cutk * cutk;

        float idet = 1.0f / det;
        float r[9] = { TWO_PI*cof00*idet, TWO_PI*cof01*idet, TWO_PI*cof02*idet,
                       TWO_PI*cof10*idet, TWO_PI*cof11*idet, TWO_PI*cof12*idet,
                       TWO_PI*cof20*idet, TWO_PI*cof21*idet, TWO_PI*cof22*idet };
        for (int q = 0; q < 9; q++) { g_recipm[q] = r[q]; s_r[q] = r[q]; }

        g_cdiag[0] = c00; g_cdiag[1] = c11; g_cdiag[2] = c22;
        g_isdiag = (c01 == 0.f && c02 == 0.f && c10 == 0.f &&
                    c12 == 0.f && c20 == 0.f && c21 == 0.f);

        g_acc_real = 0.0; g_acc_recip = 0.0; g_acc_self = 0.0; g_ticket = 0u;
    }

    if (tid < NSHIFT) {
        float sx = (float)(tid/9 - 1), sy = (float)((tid/3)%3 - 1), sz = (float)(tid%3 - 1);
        float x = sx*cell[0] + sy*cell[3] + sz*cell[6];
        float y = sx*cell[1] + sy*cell[4] + sz*cell[7];
        float z = sx*cell[2] + sy*cell[5] + sz*cell[8];
        g_shift[tid] = make_float4(x, y, z, fmaf(x,x,fmaf(y,y,z*z)));
    }
    __syncthreads();

    if (tid < n) {
        float px = pos[3*tid], py = pos[3*tid+1], pz = pos[3*tid+2];
        float q  = charges[tid];
        g_posq[tid] = make_float4(px, py, pz, q);
        g_sig[tid]  = sigtab[species[tid]];
        g_tq[tid]   = make_float4(fmaf(px,s_r[0],fmaf(py,s_r[1],pz*s_r[2])),
                                  fmaf(px,s_r[3],fmaf(py,s_r[4],pz*s_r[5])),
                                  fmaf(px,s_r[6],fmaf(py,s_r[7],pz*s_r[8])), q);
    }
}

// ==================== fused main kernel ====================
__global__ void __launch_bounds__(512, 2) k_main(int n, int npairs,
                                                 float* __restrict__ out, int grid)
{
    __shared__ float4 stq[MAXN];           // recip only
    __shared__ float4 sshift[NSHIFT];
    __shared__ float  spc[2][4][17], sps[2][4][17];
    __shared__ float  searr[40];
    __shared__ double sred[16];

    const int tid = threadIdx.x;
    const int bid = blockIdx.x;

    if (bid < NB_RECIP) {
        // ======================= reciprocal =======================
        for (int i = tid; i < n; i += 512) stq[i] = g_tq[i];
        __syncthreads();

        int wid  = tid >> 5, lane = tid & 31;
        int l    = wid >> 3;
        int sub  = wid & 7;
        int h    = sub >> 2;          // m-half: 0 -> fz -8..0, 1 -> fz 1..8
        int s4   = sub & 3;           // atom slice
        int line = bid * 2 + l;

        float qc[9], qs[9];
        #pragma unroll
        for (int e = 0; e < 9; e++) { qc[e] = 0.f; qs[e] = 0.f; }

        if (line < NLINES) {
            int fx, fy; line_to_fxy(line, fx, fy);
            float ffx = (float)fx, ffy = (float)fy;
            float moff = (float)(h * 9 - 8);

            for (int a = lane + s4*32; a < n; a += 128) {
                float4 tq = stq[a];
                float base = fmaf(ffx, tq.x, fmaf(ffy, tq.y, moff * tq.z));
                float c, s, ct, st;
                __sincosf(base, &s, &c);
                __sincosf(tq.z, &st, &ct);
                #pragma unroll
                for (int e = 0; e < 9; e++) {
                    qc[e] = fmaf(tq.w, c, qc[e]);
                    qs[e] = fmaf(tq.w, s, qs[e]);
                    float cn = fmaf(c, ct, -s*st);
                    s        = fmaf(s, ct,  c*st);
                    c = cn;
                }
            }
            #pragma unroll
            for (int e = 0; e < 9; e++) {
                #pragma unroll
                for (int off = 16; off; off >>= 1) {
                    qc[e] += __shfl_down_sync(0xFFFFFFFFu, qc[e], off);
                    qs[e] += __shfl_down_sync(0xFFFFFFFFu, qs[e], off);
                }
            }
            if (lane == 0) {
                int mb  = h * 9;
                int cnt = h ? 8 : 9;     // h=1, e=8 would be fz=9: discard
                for (int e = 0; e < cnt; e++) {
                    spc[l][s4][mb + e] = qc[e];
                    sps[l][s4][mb + e] = qs[e];
                }
            }
        }
        __syncthreads();

        if (tid < 34) {
            int l2 = tid / 17, m = tid % 17;
            int line2 = bid * 2 + l2;
            float e = 0.f;
            if (line2 < NLINES) {
                int fx2, fy2; line_to_fxy(line2, fx2, fy2);
                float w2 = (line2 == 0) ? 1.f : 2.f;
                float ffx = (float)fx2, ffy = (float)fy2, ffz = (float)(m - 8);
                float kx = ffx*g_recipm[0] + ffy*g_recipm[3] + ffz*g_recipm[6];
                float ky = ffx*g_recipm[1] + ffy*g_recipm[4] + ffz*g_recipm[7];
                float kz = ffx*g_recipm[2] + ffy*g_recipm[5] + ffz*g_recipm[8];
                float k2 = fmaf(kx, kx, fmaf(ky, ky, kz*kz));
                if (k2 > 1e-16f && k2 < g_cut2_recip) {
                    float eta = g_eta;
                    float wk = __fdividef(__expf(-0.5f * eta * eta * k2), k2);
                    float C = spc[l2][0][m] + spc[l2][1][m] + spc[l2][2][m] + spc[l2][3][m];
                    float S = sps[l2][0][m] + sps[l2][1][m] + sps[l2][2][m] + sps[l2][3][m];
                    e = w2 * wk * fmaf(C, C, S*S);
                }
            }
            searr[tid] = e;
        }
        __syncthreads();
        if (tid == 0) {
            double v = 0.0;
            for (int q2 = 0; q2 < 34; q2++) v += (double)searr[q2];
            if (v != 0.0) atomicAdd(&g_acc_recip, v);
        }
    }
    else if (bid == SELF_BID) {
        // ================= self + diagonal real-space =================
        if (tid < NSHIFT) sshift[tid] = g_shift[tid];
        __syncthreads();

        float eta = g_eta, inv_s2eta = g_inv_s2eta, cut2 = g_cut2_eff;
        float t0s = __fdividef(-0.7978845608f, eta);
        const float c0 = 0.5641895835f;

        float acc = 0.f;
        for (int i = tid; i < n; i += 512) {
            float q   = g_posq[i].w;
            float sig = g_sig[i];
            float v   = t0s + __fdividef(c0, sig);
            float invgam = rsqrtf(4.0f * sig * sig);
            #pragma unroll
            for (int m = 0; m < NSHIFT; m++) {
                float r2 = sshift[m].w;
                if (r2 > 1e-16f && r2 < cut2) {
                    float rinv = rsqrtf(r2);
                    float r    = r2 * rinv;
                    float ag   = r * invgam;
                    float eg   = (ag < 4.0f) ? erfc_fast(ag) : 0.f;
                    v = fmaf(erfc_fast(r * inv_s2eta) - eg, rinv, v);
                }
            }
            acc = fmaf(q*q, v, acc);
        }
        #pragma unroll
        for (int off = 16; off; off >>= 1)
            acc += __shfl_down_sync(0xFFFFFFFFu, acc, off);
        int warp = tid >> 5;
        if ((tid & 31) == 0) sred[warp] = (double)acc;
        __syncthreads();
        if (tid == 0) {
            double v = 0.0;
            for (int w = 0; w < 16; w++) v += sred[w];
            atomicAdd(&g_acc_self, v);
        }
    }
    else {
        // ======================= real-space pairs =======================
        if (tid < NSHIFT) sshift[tid] = g_shift[tid];
        __syncthreads();

        int t = (bid - REAL_BID0) * 512 + tid;
        float contrib = 0.f;
        if (t < npairs) {
            // decode t -> (i, j), j < i ; 8t+1 < 2^24 exact in fp32
            int i = (int)((1.0f + sqrtf(1.0f + 8.0f * (float)t)) * 0.5f);
            while (i * (i - 1) / 2 > t) i--;
            while ((i + 1) * i / 2 <= t) i++;
            int j = t - i * (i - 1) / 2;

            float4 a = g_posq[i];
            float4 b = g_posq[j];
            float dx = b.x - a.x, dy = b.y - a.y, dz = b.z - a.z;
            float si = g_sig[i], sj = g_sig[j];
            float inv_s2gam = rsqrtf(2.0f * fmaf(si, si, sj * sj));
            float inv_s2eta = g_inv_s2eta;
            float cut2      = g_cut2_eff;

            unsigned mask = 0u;
            if (g_isdiag) {
                float cx = g_cdiag[0], cy = g_cdiag[1], cz = g_cdiag[2];
                unsigned mx = 0u, my = 0u, mz = 0u;
                float v0;
                v0 = dx - cx; if (v0*v0 < cut2) mx |= 1u;
                v0 = dx;      if (v0*v0 < cut2) mx |= 2u;
                v0 = dx + cx; if (v0*v0 < cut2) mx |= 4u;
                v0 = dy - cy; if (v0*v0 < cut2) my |= 1u;
                v0 = dy;      if (v0*v0 < cut2) my |= 2u;
                v0 = dy + cy; if (v0*v0 < cut2) my |= 4u;
                v0 = dz - cz; if (v0*v0 < cut2) mz |= 1u;
                v0 = dz;      if (v0*v0 < cut2) mz |= 2u;
                v0 = dz + cz; if (v0*v0 < cut2) mz |= 4u;
                unsigned myz = ((my & 1u) ? mz : 0u)
                             | ((my & 2u) ? (mz << 3) : 0u)
                             | ((my & 4u) ? (mz << 6) : 0u);
                mask = ((mx & 1u) ? myz : 0u)
                     | ((mx & 2u) ? (myz << 9)  : 0u)
                     | ((mx & 4u) ? (myz << 18) : 0u);
            } else {
                #pragma unroll
                for (int m = 0; m < NSHIFT; m++) {
                    float ddx = dx + sshift[m].x;
                    float ddy = dy + sshift[m].y;
                    float ddz = dz + sshift[m].z;
                    float r2  = fmaf(ddx, ddx, fmaf(ddy, ddy, ddz*ddz));
                    if (r2 > 1e-16f && r2 < cut2) mask |= (1u << m);
                }
            }

            float s = 0.f;
            while (mask) {
                int m = __ffs(mask) - 1;
                mask &= mask - 1;
                float4 sm = sshift[m];
                float ddx = dx + sm.x;
                float ddy = dy + sm.y;
                float ddz = dz + sm.z;
                float r2  = fmaf(ddx, ddx, fmaf(ddy, ddy, ddz*ddz));
                if (r2 > 1e-16f && r2 < cut2) {
                    float rinv = rsqrtf(r2);
                    float r    = r2 * rinv;
                    float ag   = r * inv_s2gam;
                    float eg   = (ag < 4.0f) ? erfc_fast(ag) : 0.f;
                    s = fmaf(erfc_fast(r * inv_s2eta) - eg, rinv, s);
                }
            }
            contrib = 2.f * s * a.w * b.w;
        }

        #pragma unroll
        for (int off = 16; off; off >>= 1)
            contrib += __shfl_down_sync(0xFFFFFFFFu, contrib, off);
        int warp = tid >> 5;
        if ((tid & 31) == 0) sred[warp] = (double)contrib;
        __syncthreads();
        if (tid < 32) {
            double v = (tid < 16) ? sred[tid] : 0.0;
            #pragma unroll
            for (int off = 8; off; off >>= 1)
                v += __shfl_down_sync(0xFFFFFFFFu, v, off);
            if (tid == 0 && v != 0.0) atomicAdd(&g_acc_real, v);
        }
    }

    // ---- last block to finish finalizes (setup re-zeros each replay) ----
    __syncthreads();
    if (tid == 0) {
        __threadfence();
        unsigned ticket = atomicAdd(&g_ticket, 1u);
        if (ticket == (unsigned)grid - 1u) {
            const double COEF    = 14.399645478425668;
            const double FOUR_PI = 12.566370614359172953850573533118;
            double ar = *(volatile double*)&g_acc_real;
            double ak = *(volatile double*)&g_acc_recip;
            double as = *(volatile double*)&g_acc_self;
            double e  = 0.5 * COEF * (ar + as + (FOUR_PI / (double)g_vol) * ak);
            out[0] = (float)e;
        }
    }
}

extern "C" void kernel_launch(void* const* d_in, const int* in_sizes, int n_in,
                              void* d_out, int out_size)
{
    const float* pos     = (const float*)d_in[0];
    const float* cell    = (const float*)d_in[1];
    const float* charges = (const float*)d_in[2];
    const float* sigtab  = (const float*)d_in[3];
    const int*   species = (const int*)  d_in[4];

    int n = in_sizes[0] / 3;
    int npairs  = n * (n - 1) / 2;
    int nb_real = (npairs + 511) / 512;
    int grid    = REAL_BID0 + nb_real;

    k_setup<<<1, 768>>>(cell, sigtab, pos, charges, species, n);
    k_main<<<grid, 512>>>(n, npairs, (float*)d_out, grid);
}

// round 10
// speedup vs baseline: 1.2911x; 1.1216x over previous
#include <cuda_runtime.h>
#include <math.h>

#define MAXN     1024
#define NSHIFT   27
#define NLINES   145          // half-space (fx,fy) lines: (0,0) + (0,1..8) + (1..8, -8..8)
#define NB_RECIP 73           // 2 lines per 512-thread block
#define SELF_BID NB_RECIP
#define REAL_BID0 (NB_RECIP + 1)

// -------- device globals --------
__device__ float4 g_posq[MAXN];        // x,y,z,q
__device__ float4 g_tq[MAXN];          // recip theta factors (t0,t1,t2,q)
__device__ float  g_sig[MAXN];
__device__ float4 g_shift[NSHIFT];     // xyz shift, w=|s|^2
__device__ float  g_recipm[9];
__device__ float  g_eta, g_inv_s2eta, g_cut2_eff, g_cut2_recip, g_vol;
__device__ float  g_cdiag[3];
__device__ int    g_isdiag;
__device__ double g_acc_real, g_acc_recip, g_acc_self;

// fast erfc: Abramowitz & Stegun 7.1.26, |abs err| <= 1.5e-7
// For large x, __expf(-x^2) underflows to 0 -> returns 0 (safe for any x >= 0).
__device__ __forceinline__ float erfc_fast(float x)
{
    float t = __fdividef(1.0f, fmaf(0.3275911f, x, 1.0f));
    float p = t * fmaf(t, fmaf(t, fmaf(t, fmaf(t, 1.061405429f, -1.453152027f),
                        1.421413741f), -0.284496736f), 0.254829592f);
    return p * __expf(-x * x);
}

__device__ __forceinline__ void line_to_fxy(int line, int& fx, int& fy)
{
    if (line == 0)      { fx = 0; fy = 0; }
    else if (line <= 8) { fx = 0; fy = line; }
    else { int u = line - 9; fx = u / 17 + 1; fy = u % 17 - 8; }
}

// -------- setup: one block, 768 threads, all fp32 --------
__global__ void __launch_bounds__(768) k_setup(
    const float* __restrict__ cell,  const float* __restrict__ sigtab,
    const float* __restrict__ pos,   const float* __restrict__ charges,
    const int*   __restrict__ species, int n)
{
    __shared__ float s_r[9];
    int tid = threadIdx.x;

    if (tid == 0) {
        float c00 = cell[0], c01 = cell[1], c02 = cell[2];
        float c10 = cell[3], c11 = cell[4], c12 = cell[5];
        float c20 = cell[6], c21 = cell[7], c22 = cell[8];

        float cof00 =  (c11*c22 - c12*c21);
        float cof01 = -(c10*c22 - c12*c20);
        float cof02 =  (c10*c21 - c11*c20);
        float cof10 = -(c01*c22 - c02*c21);
        float cof11 =  (c00*c22 - c02*c20);
        float cof12 = -(c00*c21 - c01*c20);
        float cof20 =  (c01*c12 - c02*c11);
        float cof21 = -(c00*c12 - c02*c10);
        float cof22 =  (c00*c11 - c01*c10);

        float det = c00*cof00 + c01*cof01 + c02*cof02;
        float vol = fabsf(det);
        g_vol = vol;

        const float TWO_PI = 6.2831853071795864769f;
        float eta = powf(vol * vol / (float)n, 1.0f / 6.0f) * rsqrtf(TWO_PI);
        g_eta       = eta;
        g_inv_s2eta = 1.0f / (1.4142135623730951f * eta);
        // tightened: arg_eta < 4 -> erfc < 1.5e-8 (below approx error); ref cut = 36.84 eta^2
        g_cut2_eff  = 32.0f * eta * eta;
        const float SQRT_2LOG = 6.0697086f;
        float cutk = SQRT_2LOG / eta;
        g_cut2_recip = cutk * cutk;

        float idet = 1.0f / det;
        float r[9] = { TWO_PI*cof00*idet, TWO_PI*cof01*idet, TWO_PI*cof02*idet,
                       TWO_PI*cof10*idet, TWO_PI*cof11*idet, TWO_PI*cof12*idet,
                       TWO_PI*cof20*idet, TWO_PI*cof21*idet, TWO_PI*cof22*idet };
        for (int q = 0; q < 9; q++) { g_recipm[q] = r[q]; s_r[q] = r[q]; }

        g_cdiag[0] = c00; g_cdiag[1] = c11; g_cdiag[2] = c22;
        g_isdiag = (c01 == 0.f && c02 == 0.f && c10 == 0.f &&
                    c12 == 0.f && c20 == 0.f && c21 == 0.f);

        g_acc_real = 0.0; g_acc_recip = 0.0; g_acc_self = 0.0;
    }

    if (tid < NSHIFT) {
        float sx = (float)(tid/9 - 1), sy = (float)((tid/3)%3 - 1), sz = (float)(tid%3 - 1);
        float x = sx*cell[0] + sy*cell[3] + sz*cell[6];
        float y = sx*cell[1] + sy*cell[4] + sz*cell[7];
        float z = sx*cell[2] + sy*cell[5] + sz*cell[8];
        g_shift[tid] = make_float4(x, y, z, fmaf(x,x,fmaf(y,y,z*z)));
    }
    __syncthreads();

    if (tid < n) {
        float px = pos[3*tid], py = pos[3*tid+1], pz = pos[3*tid+2];
        float q  = charges[tid];
        g_posq[tid] = make_float4(px, py, pz, q);
        g_sig[tid]  = sigtab[species[tid]];
        g_tq[tid]   = make_float4(fmaf(px,s_r[0],fmaf(py,s_r[1],pz*s_r[2])),
                                  fmaf(px,s_r[3],fmaf(py,s_r[4],pz*s_r[5])),
                                  fmaf(px,s_r[6],fmaf(py,s_r[7],pz*s_r[8])), q);
    }
}

// ==================== fused main kernel ====================
__global__ void __launch_bounds__(512, 3) k_main(int n, int npairs)
{
    __shared__ float4 stq[MAXN];           // recip only
    __shared__ float4 sshift[NSHIFT];
    __shared__ float  spc[2][2][17], sps[2][2][17];
    __shared__ float  searr[40];
    __shared__ double sred[16];

    const int tid = threadIdx.x;
    const int bid = blockIdx.x;

    if (bid < NB_RECIP) {
        // ======================= reciprocal =======================
        // 2 lines/block; per line: 4 m-quarters x 2 atom slices = 8 warps
        for (int i = tid; i < n; i += 512) stq[i] = g_tq[i];
        __syncthreads();

        int wid  = tid >> 5, lane = tid & 31;
        int l    = wid >> 3;
        int sub  = wid & 7;
        int q4   = sub >> 1;          // m-quarter 0..3
        int s2   = sub & 1;           // atom slice
        int line = bid * 2 + l;

        // quarter q4: m-base and count over fz = -8..8 (17 values: 5+4+4+4)
        int   mb   = (q4 == 0) ? 0 : (q4 == 1 ? 5 : (q4 == 2 ? 9 : 13));
        int   cnt  = (q4 == 0) ? 5 : 4;
        float moff = (float)(mb - 8);

        float qc[5], qs[5];
        #pragma unroll
        for (int e = 0; e < 5; e++) { qc[e] = 0.f; qs[e] = 0.f; }

        if (line < NLINES) {
            int fx, fy; line_to_fxy(line, fx, fy);
            float ffx = (float)fx, ffy = (float)fy;

            for (int a = lane + s2*32; a < n; a += 64) {
                float4 tq = stq[a];
                float base = fmaf(ffx, tq.x, fmaf(ffy, tq.y, moff * tq.z));
                float c, s, ct, st;
                __sincosf(base, &s, &c);
                __sincosf(tq.z, &st, &ct);
                #pragma unroll
                for (int e = 0; e < 5; e++) {
                    qc[e] = fmaf(tq.w, c, qc[e]);
                    qs[e] = fmaf(tq.w, s, qs[e]);
                    float cn = fmaf(c, ct, -s*st);
                    s        = fmaf(s, ct,  c*st);
                    c = cn;
                }
            }
            #pragma unroll
            for (int e = 0; e < 5; e++) {
                #pragma unroll
                for (int off = 16; off; off >>= 1) {
                    qc[e] += __shfl_down_sync(0xFFFFFFFFu, qc[e], off);
                    qs[e] += __shfl_down_sync(0xFFFFFFFFu, qs[e], off);
                }
            }
            if (lane == 0) {
                for (int e = 0; e < cnt; e++) {
                    spc[l][s2][mb + e] = qc[e];
                    sps[l][s2][mb + e] = qs[e];
                }
            }
        }
        __syncthreads();

        if (tid < 34) {
            int l2 = tid / 17, m = tid % 17;
            int line2 = bid * 2 + l2;
            float e = 0.f;
            if (line2 < NLINES) {
                int fx2, fy2; line_to_fxy(line2, fx2, fy2);
                float w2 = (line2 == 0) ? 1.f : 2.f;
                float ffx = (float)fx2, ffy = (float)fy2, ffz = (float)(m - 8);
                float kx = ffx*g_recipm[0] + ffy*g_recipm[3] + ffz*g_recipm[6];
                float ky = ffx*g_recipm[1] + ffy*g_recipm[4] + ffz*g_recipm[7];
                float kz = ffx*g_recipm[2] + ffy*g_recipm[5] + ffz*g_recipm[8];
                float k2 = fmaf(kx, kx, fmaf(ky, ky, kz*kz));
                if (k2 > 1e-16f && k2 < g_cut2_recip) {
                    float eta = g_eta;
                    float wk = __fdividef(__expf(-0.5f * eta * eta * k2), k2);
                    float C = spc[l2][0][m] + spc[l2][1][m];
                    float S = sps[l2][0][m] + sps[l2][1][m];
                    e = w2 * wk * fmaf(C, C, S*S);
                }
            }
            searr[tid] = e;
        }
        __syncthreads();
        if (tid == 0) {
            double v = 0.0;
            for (int q2 = 0; q2 < 34; q2++) v += (double)searr[q2];
            if (v != 0.0) atomicAdd(&g_acc_recip, v);
        }
    }
    else if (bid == SELF_BID) {
        // ================= self + diagonal real-space =================
        if (tid < NSHIFT) sshift[tid] = g_shift[tid];
        __syncthreads();

        float eta = g_eta, inv_s2eta = g_inv_s2eta, cut2 = g_cut2_eff;
        float t0s = __fdividef(-0.7978845608f, eta);
        const float c0 = 0.5641895835f;

        float acc = 0.f;
        for (int i = tid; i < n; i += 512) {
            float q   = g_posq[i].w;
            float sig = g_sig[i];
            float v   = t0s + __fdividef(c0, sig);
            float invgam = rsqrtf(4.0f * sig * sig);
            #pragma unroll
            for (int m = 0; m < NSHIFT; m++) {
                float r2 = sshift[m].w;
                if (r2 > 1e-16f && r2 < cut2) {
                    float rinv = rsqrtf(r2);
                    float r    = r2 * rinv;
                    v = fmaf(erfc_fast(r * inv_s2eta) - erfc_fast(r * invgam), rinv, v);
                }
            }
            acc = fmaf(q*q, v, acc);
        }
        #pragma unroll
        for (int off = 16; off; off >>= 1)
            acc += __shfl_down_sync(0xFFFFFFFFu, acc, off);
        int warp = tid >> 5;
        if ((tid & 31) == 0) sred[warp] = (double)acc;
        __syncthreads();
        if (tid == 0) {
            double v = 0.0;
            for (int w = 0; w < 16; w++) v += sred[w];
            atomicAdd(&g_acc_self, v);
        }
    }
    else {
        // ======================= real-space pairs =======================
        if (tid < NSHIFT) sshift[tid] = g_shift[tid];
        __syncthreads();

        int t = (bid - REAL_BID0) * 512 + tid;
        float contrib = 0.f;
        if (t < npairs) {
            // decode t -> (i, j), j < i ; 8t+1 < 2^24 exact in fp32
            int i = (int)((1.0f + sqrtf(1.0f + 8.0f * (float)t)) * 0.5f);
            while (i * (i - 1) / 2 > t) i--;
            while ((i + 1) * i / 2 <= t) i++;
            int j = t - i * (i - 1) / 2;

            float4 a = g_posq[i];
            float4 b = g_posq[j];
            float dx = b.x - a.x, dy = b.y - a.y, dz = b.z - a.z;
            float si = g_sig[i], sj = g_sig[j];
            float inv_s2gam = rsqrtf(2.0f * fmaf(si, si, sj * sj));
            float inv_s2eta = g_inv_s2eta;
            float cut2      = g_cut2_eff;

            unsigned mask = 0u;
            if (g_isdiag) {
                // separable per-axis candidate filter (necessary per axis).
                // False positives are harmless: both erfc underflow to 0.
                float cx = g_cdiag[0], cy = g_cdiag[1], cz = g_cdiag[2];
                unsigned mx = 0u, my = 0u, mz = 0u;
                float v0;
                v0 = dx - cx; if (v0*v0 < cut2) mx |= 1u;
                v0 = dx;      if (v0*v0 < cut2) mx |= 2u;
                v0 = dx + cx; if (v0*v0 < cut2) mx |= 4u;
                v0 = dy - cy; if (v0*v0 < cut2) my |= 1u;
                v0 = dy;      if (v0*v0 < cut2) my |= 2u;
                v0 = dy + cy; if (v0*v0 < cut2) my |= 4u;
                v0 = dz - cz; if (v0*v0 < cut2) mz |= 1u;
                v0 = dz;      if (v0*v0 < cut2) mz |= 2u;
                v0 = dz + cz; if (v0*v0 < cut2) mz |= 4u;
                unsigned myz = ((my & 1u) ? mz : 0u)
                             | ((my & 2u) ? (mz << 3) : 0u)
                             | ((my & 4u) ? (mz << 6) : 0u);
                mask = ((mx & 1u) ? myz : 0u)
                     | ((mx & 2u) ? (myz << 9)  : 0u)
                     | ((mx & 4u) ? (myz << 18) : 0u);
            } else {
                #pragma unroll
                for (int m = 0; m < NSHIFT; m++) {
                    float ddx = dx + sshift[m].x;
                    float ddy = dy + sshift[m].y;
                    float ddz = dz + sshift[m].z;
                    float r2  = fmaf(ddx, ddx, fmaf(ddy, ddy, ddz*ddz));
                    if (r2 > 1e-16f && r2 < cut2) mask |= (1u << m);
                }
            }

            float s = 0.f;
            while (mask) {
                int m = __ffs(mask) - 1;
                mask &= mask - 1;
                float4 sm = sshift[m];
                float ddx = dx + sm.x;
                float ddy = dy + sm.y;
                float ddz = dz + sm.z;
                float r2  = fmaf(ddx, ddx, fmaf(ddy, ddy, ddz*ddz));
                float rinv = rsqrtf(r2);
                float r    = r2 * rinv;
                s = fmaf(erfc_fast(r * inv_s2eta) - erfc_fast(r * inv_s2gam), rinv, s);
            }
            contrib = 2.f * s * a.w * b.w;
        }

        #pragma unroll
        for (int off = 16; off; off >>= 1)
            contrib += __shfl_down_sync(0xFFFFFFFFu, contrib, off);
        int warp = tid >> 5;
        if ((tid & 31) == 0) sred[warp] = (double)contrib;
        __syncthreads();
        if (tid < 32) {
            double v = (tid < 16) ? sred[tid] : 0.0;
            #pragma unroll
            for (int off = 8; off; off >>= 1)
                v += __shfl_down_sync(0xFFFFFFFFu, v, off);
            if (tid == 0 && v != 0.0) atomicAdd(&g_acc_real, v);
        }
    }
}

// -------- finalize: tiny trailing kernel --------
__global__ void k_fin(float* __restrict__ out)
{
    const double COEF    = 14.399645478425668;
    const double FOUR_PI = 12.566370614359172953850573533118;
    double e = 0.5 * COEF * (g_acc_real + g_acc_self
                             + (FOUR_PI / (double)g_vol) * g_acc_recip);
    out[0] = (float)e;
}

extern "C" void kernel_launch(void* const* d_in, const int* in_sizes, int n_in,
                              void* d_out, int out_size)
{
    const float* pos     = (const float*)d_in[0];
    const float* cell    = (const float*)d_in[1];
    const float* charges = (const float*)d_in[2];
    const float* sigtab  = (const float*)d_in[3];
    const int*   species = (const int*)  d_in[4];

    int n = in_sizes[0] / 3;
    int npairs  = n * (n - 1) / 2;
    int nb_real = (npairs + 511) / 512;
    int grid    = REAL_BID0 + nb_real;

    k_setup<<<1, 768>>>(cell, sigtab, pos, charges, species, n);
    k_main<<<grid, 512>>>(n, npairs);
    k_fin<<<1, 1>>>((float*)d_out);
}

// round 12
// speedup vs baseline: 1.4280x; 1.1061x over previous
#include <cuda_runtime.h>
#include <math.h>

#define MAXN     1024
#define NSHIFT   27
#define NLINES   145          // half-space (fx,fy) lines: (0,0) + (0,1..8) + (1..8, -8..8)
#define NB_RECIP 73           // 2 lines per 512-thread block
#define SELF_BID NB_RECIP
#define REAL_BID0 (NB_RECIP + 1)

// -------- device accumulators: zero at module load; k_fin re-zeros each run --------
__device__ double g_acc_real, g_acc_recip, g_acc_self;
__device__ float  g_vol;

// fast erfc: Abramowitz & Stegun 7.1.26, |abs err| <= 1.5e-7
// For large x, __expf(-x^2) underflows to 0 -> returns 0 (safe for any x >= 0).
__device__ __forceinline__ float erfc_fast(float x)
{
    float t = __fdividef(1.0f, fmaf(0.3275911f, x, 1.0f));
    float p = t * fmaf(t, fmaf(t, fmaf(t, fmaf(t, 1.061405429f, -1.453152027f),
                        1.421413741f), -0.284496736f), 0.254829592f);
    return p * __expf(-x * x);
}

__device__ __forceinline__ void line_to_fxy(int line, int& fx, int& fy)
{
    if (line == 0)      { fx = 0; fy = 0; }
    else if (line <= 8) { fx = 0; fy = line; }
    else { int u = line - 9; fx = u / 17 + 1; fy = u % 17 - 8; }
}

// ==================== single fused kernel ====================
__global__ void __launch_bounds__(512, 3) k_main(
    const float* __restrict__ pos,     const float* __restrict__ cell,
    const float* __restrict__ charges, const float* __restrict__ sigtab,
    const int*   __restrict__ species, int n, int npairs)
{
    __shared__ float4 stq[MAXN];           // recip only
    __shared__ float4 sshift[NSHIFT];
    __shared__ float  spc[2][2][17], sps[2][2][17];
    __shared__ float  searr[40];
    __shared__ double sred[16];

    const int tid = threadIdx.x;
    const int bid = blockIdx.x;

    // ---- uniform fp32 scalar prologue (cheap; cell is L2/const-cached) ----
    float c00 = __ldg(cell+0), c01 = __ldg(cell+1), c02 = __ldg(cell+2);
    float c10 = __ldg(cell+3), c11 = __ldg(cell+4), c12 = __ldg(cell+5);
    float c20 = __ldg(cell+6), c21 = __ldg(cell+7), c22 = __ldg(cell+8);

    float cof00 =  (c11*c22 - c12*c21);
    float cof01 = -(c10*c22 - c12*c20);
    float cof02 =  (c10*c21 - c11*c20);
    float cof10 = -(c01*c22 - c02*c21);
    float cof11 =  (c00*c22 - c02*c20);
    float cof12 = -(c00*c21 - c01*c20);
    float cof20 =  (c01*c12 - c02*c11);
    float cof21 = -(c00*c12 - c02*c10);
    float cof22 =  (c00*c11 - c01*c10);

    float det = c00*cof00 + c01*cof01 + c02*cof02;
    float vol = fabsf(det);

    const float TWO_PI = 6.2831853071795864769f;
    float eta = powf(vol * vol / (float)n, 1.0f / 6.0f) * rsqrtf(TWO_PI);
    float inv_s2eta = 1.0f / (1.4142135623730951f * eta);
    // tightened: arg_eta < 4 -> erfc < 1.5e-8 (below approx error); ref cut = 36.84 eta^2
    float cut2 = 32.0f * eta * eta;

    if (bid < NB_RECIP) {
        // ======================= reciprocal =======================
        const float SQRT_2LOG = 6.0697086f;
        float cutk = SQRT_2LOG / eta;
        float cut2_recip = cutk * cutk;

        float idet = 1.0f / det;
        float r0 = TWO_PI*cof00*idet, r1 = TWO_PI*cof01*idet, r2c = TWO_PI*cof02*idet;
        float r3 = TWO_PI*cof10*idet, r4 = TWO_PI*cof11*idet, r5 = TWO_PI*cof12*idet;
        float r6 = TWO_PI*cof20*idet, r7 = TWO_PI*cof21*idet, r8 = TWO_PI*cof22*idet;

        // stage theta factors (t0,t1,t2,q), computed on the fly
        for (int i = tid; i < n; i += 512) {
            float px = pos[3*i], py = pos[3*i+1], pz = pos[3*i+2];
            stq[i] = make_float4(fmaf(px,r0,fmaf(py,r1,pz*r2c)),
                                 fmaf(px,r3,fmaf(py,r4,pz*r5)),
                                 fmaf(px,r6,fmaf(py,r7,pz*r8)), charges[i]);
        }
        __syncthreads();

        int wid  = tid >> 5, lane = tid & 31;
        int l    = wid >> 3;
        int sub  = wid & 7;
        int q4   = sub >> 1;          // m-quarter 0..3
        int s2   = sub & 1;           // atom slice
        int line = bid * 2 + l;

        int   mb   = (q4 == 0) ? 0 : (q4 == 1 ? 5 : (q4 == 2 ? 9 : 13));
        int   cnt  = (q4 == 0) ? 5 : 4;
        float moff = (float)(mb - 8);

        float qc[5], qs[5];
        #pragma unroll
        for (int e = 0; e < 5; e++) { qc[e] = 0.f; qs[e] = 0.f; }

        if (line < NLINES) {
            int fx, fy; line_to_fxy(line, fx, fy);
            float ffx = (float)fx, ffy = (float)fy;

            for (int a = lane + s2*32; a < n; a += 64) {
                float4 tq = stq[a];
                float base = fmaf(ffx, tq.x, fmaf(ffy, tq.y, moff * tq.z));
                float c, s, ct, st;
                __sincosf(base, &s, &c);
                __sincosf(tq.z, &st, &ct);
                #pragma unroll
                for (int e = 0; e < 5; e++) {
                    qc[e] = fmaf(tq.w, c, qc[e]);
                    qs[e] = fmaf(tq.w, s, qs[e]);
                    float cn = fmaf(c, ct, -s*st);
                    s        = fmaf(s, ct,  c*st);
                    c = cn;
                }
            }
            #pragma unroll
            for (int e = 0; e < 5; e++) {
                #pragma unroll
                for (int off = 16; off; off >>= 1) {
                    qc[e] += __shfl_down_sync(0xFFFFFFFFu, qc[e], off);
                    qs[e] += __shfl_down_sync(0xFFFFFFFFu, qs[e], off);
                }
            }
            if (lane == 0) {
                for (int e = 0; e < cnt; e++) {
                    spc[l][s2][mb + e] = qc[e];
                    sps[l][s2][mb + e] = qs[e];
                }
            }
        }
        __syncthreads();

        if (tid < 34) {
            int l2 = tid / 17, m = tid % 17;
            int line2 = bid * 2 + l2;
            float e = 0.f;
            if (line2 < NLINES) {
                int fx2, fy2; line_to_fxy(line2, fx2, fy2);
                float w2 = (line2 == 0) ? 1.f : 2.f;
                float ffx = (float)fx2, ffy = (float)fy2, ffz = (float)(m - 8);
                float kx = ffx*r0 + ffy*r3 + ffz*r6;
                float ky = ffx*r1 + ffy*r4 + ffz*r7;
                float kz = ffx*r2c + ffy*r5 + ffz*r8;
                float k2 = fmaf(kx, kx, fmaf(ky, ky, kz*kz));
                if (k2 > 1e-16f && k2 < cut2_recip) {
                    float wk = __fdividef(__expf(-0.5f * eta * eta * k2), k2);
                    float C = spc[l2][0][m] + spc[l2][1][m];
                    float S = sps[l2][0][m] + sps[l2][1][m];
                    e = w2 * wk * fmaf(C, C, S*S);
                }
            }
            searr[tid] = e;
        }
        __syncthreads();
        if (tid == 0) {
            double v = 0.0;
            for (int q2 = 0; q2 < 34; q2++) v += (double)searr[q2];
            if (v != 0.0) atomicAdd(&g_acc_recip, v);
            g_vol = vol;
        }
    }
    else if (bid == SELF_BID) {
        // ================= self + diagonal real-space =================
        if (tid < NSHIFT) {
            float sx = (float)(tid/9 - 1), sy = (float)((tid/3)%3 - 1), sz = (float)(tid%3 - 1);
            float x = sx*c00 + sy*c10 + sz*c20;
            float y = sx*c01 + sy*c11 + sz*c21;
            float z = sx*c02 + sy*c12 + sz*c22;
            sshift[tid] = make_float4(x, y, z, fmaf(x,x,fmaf(y,y,z*z)));
        }
        __syncthreads();

        float t0s = __fdividef(-0.7978845608f, eta);
        const float c0 = 0.5641895835f;

        float acc = 0.f;
        for (int i = tid; i < n; i += 512) {
            float q   = charges[i];
            float sig = sigtab[species[i]];
            float v   = t0s + __fdividef(c0, sig);
            float invgam = rsqrtf(4.0f * sig * sig);
            #pragma unroll
            for (int m = 0; m < NSHIFT; m++) {
                float r2 = sshift[m].w;
                if (r2 > 1e-16f && r2 < cut2) {
                    float rinv = rsqrtf(r2);
                    float r    = r2 * rinv;
                    v = fmaf(erfc_fast(r * inv_s2eta) - erfc_fast(r * invgam), rinv, v);
                }
            }
            acc = fmaf(q*q, v, acc);
        }
        #pragma unroll
        for (int off = 16; off; off >>= 1)
            acc += __shfl_down_sync(0xFFFFFFFFu, acc, off);
        int warp = tid >> 5;
        if ((tid & 31) == 0) sred[warp] = (double)acc;
        __syncthreads();
        if (tid == 0) {
            double v = 0.0;
            for (int w = 0; w < 16; w++) v += sred[w];
            atomicAdd(&g_acc_self, v);
        }
    }
    else {
        // ======================= real-space pairs =======================
        bool isdiag = (c01 == 0.f && c02 == 0.f && c10 == 0.f &&
                       c12 == 0.f && c20 == 0.f && c21 == 0.f);
        if (tid < NSHIFT) {
            float sx = (float)(tid/9 - 1), sy = (float)((tid/3)%3 - 1), sz = (float)(tid%3 - 1);
            float x = sx*c00 + sy*c10 + sz*c20;
            float y = sx*c01 + sy*c11 + sz*c21;
            float z = sx*c02 + sy*c12 + sz*c22;
            sshift[tid] = make_float4(x, y, z, fmaf(x,x,fmaf(y,y,z*z)));
        }
        __syncthreads();

        int t = (bid - REAL_BID0) * 512 + tid;
        float contrib = 0.f;
        if (t < npairs) {
            // decode t -> (i, j), j < i ; 8t+1 < 2^24 exact in fp32
            int i = (int)((1.0f + sqrtf(1.0f + 8.0f * (float)t)) * 0.5f);
            while (i * (i - 1) / 2 > t) i--;
            while ((i + 1) * i / 2 <= t) i++;
            int j = t - i * (i - 1) / 2;

            float aix = pos[3*i], aiy = pos[3*i+1], aiz = pos[3*i+2];
            float bjx = pos[3*j], bjy = pos[3*j+1], bjz = pos[3*j+2];
            float qi = charges[i], qj = charges[j];
            float dx = bjx - aix, dy = bjy - aiy, dz = bjz - aiz;
            float si = sigtab[species[i]], sj = sigtab[species[j]];
            float inv_s2gam = rsqrtf(2.0f * fmaf(si, si, sj * sj));

            unsigned mask = 0u;
            if (isdiag) {
                // separable per-axis candidate filter (necessary per axis).
                // False positives are harmless: both erfc underflow to 0.
                unsigned mx = 0u, my = 0u, mz = 0u;
                float v0;
                v0 = dx - c00; if (v0*v0 < cut2) mx |= 1u;
                v0 = dx;       if (v0*v0 < cut2) mx |= 2u;
                v0 = dx + c00; if (v0*v0 < cut2) mx |= 4u;
                v0 = dy - c11; if (v0*v0 < cut2) my |= 1u;
                v0 = dy;       if (v0*v0 < cut2) my |= 2u;
                v0 = dy + c11; if (v0*v0 < cut2) my |= 4u;
                v0 = dz - c22; if (v0*v0 < cut2) mz |= 1u;
                v0 = dz;       if (v0*v0 < cut2) mz |= 2u;
                v0 = dz + c22; if (v0*v0 < cut2) mz |= 4u;
                unsigned myz = ((my & 1u) ? mz : 0u)
                             | ((my & 2u) ? (mz << 3) : 0u)
                             | ((my & 4u) ? (mz << 6) : 0u);
                mask = ((mx & 1u) ? myz : 0u)
                     | ((mx & 2u) ? (myz << 9)  : 0u)
                     | ((mx & 4u) ? (myz << 18) : 0u);
            } else {
                #pragma unroll
                for (int m = 0; m < NSHIFT; m++) {
                    float ddx = dx + sshift[m].x;
                    float ddy = dy + sshift[m].y;
                    float ddz = dz + sshift[m].z;
                    float r2  = fmaf(ddx, ddx, fmaf(ddy, ddy, ddz*ddz));
                    if (r2 > 1e-16f && r2 < cut2) mask |= (1u << m);
                }
            }

            float s = 0.f;
            while (mask) {
                int m = __ffs(mask) - 1;
                mask &= mask - 1;
                float4 sm = sshift[m];
                float ddx = dx + sm.x;
                float ddy = dy + sm.y;
                float ddz = dz + sm.z;
                float r2  = fmaf(ddx, ddx, fmaf(ddy, ddy, ddz*ddz));
                float rinv = rsqrtf(r2);
                float r    = r2 * rinv;
                s = fmaf(erfc_fast(r * inv_s2eta) - erfc_fast(r * inv_s2gam), rinv, s);
            }
            contrib = 2.f * s * qi * qj;
        }

        #pragma unroll
        for (int off = 16; off; off >>= 1)
            contrib += __shfl_down_sync(0xFFFFFFFFu, contrib, off);
        int warp = tid >> 5;
        if ((tid & 31) == 0) sred[warp] = (double)contrib;
        __syncthreads();
        if (tid < 32) {
            double v = (tid < 16) ? sred[tid] : 0.0;
            #pragma unroll
            for (int off = 8; off; off >>= 1)
                v += __shfl_down_sync(0xFFFFFFFFu, v, off);
            if (tid == 0 && v != 0.0) atomicAdd(&g_acc_real, v);
        }
    }
}

// -------- finalize: read, write out, reset accumulators for next replay --------
__global__ void k_fin(float* __restrict__ out)
{
    const double COEF    = 14.399645478425668;
    const double FOUR_PI = 12.566370614359172953850573533118;
    double e = 0.5 * COEF * (g_acc_real + g_acc_self
                             + (FOUR_PI / (double)g_vol) * g_acc_recip);
    out[0] = (float)e;
    g_acc_real = 0.0; g_acc_recip = 0.0; g_acc_self = 0.0;
}

extern "C" void kernel_launch(void* const* d_in, const int* in_sizes, int n_in,
                              void* d_out, int out_size)
{
    const float* pos     = (const float*)d_in[0];
    const float* cell    = (const float*)d_in[1];
    const float* charges = (const float*)d_in[2];
    const float* sigtab  = (const float*)d_in[3];
    const int*   species = (const int*)  d_in[4];

    int n = in_sizes[0] / 3;
    int npairs  = n * (n - 1) / 2;
    int nb_real = (npairs + 511) / 512;
    int grid    = REAL_BID0 + nb_real;

    k_main<<<grid, 512>>>(pos, cell, charges, sigtab, species, n, npairs);
    k_fin<<<1, 1>>>((float*)d_out);
}